// round 1
// baseline (speedup 1.0000x reference)
#include <cuda_runtime.h>
#include <cuda_bf16.h>
#include <math.h>

// Problem constants (fixed by setup_inputs)
#define BATCH 2
#define SEQ   2048
#define DIM   1024
#define HEADS 8
#define MROWS (BATCH*SEQ)   // 4096
#define EPSLN 1e-5f

// Scratch (device globals; allocation-free per harness rules)
__device__ float g_q[BATCH*SEQ*DIM];        // 16 MB
__device__ float g_sc[BATCH*SEQ*SEQ];       // 32 MB
__device__ float g_head[BATCH*SEQ*DIM];     // 16 MB
__device__ float g_h[BATCH*SEQ*DIM];        // 16 MB
__device__ float g_t[BATCH*SEQ*DIM];        // 16 MB
__device__ float g_weff[DIM*DIM];           // 4 MB

// ---------------- tiled SGEMM: C = A[MxK] * B[KxN] (+ epilogue) -------------
// BM=BN=128, BK=8, TM=TN=8, 256 threads.
#define BM 128
#define BN 128
#define BKD 8
#define TM 8
#define TN 8

// EPI: 0 = none, 1 = +res, 2 = +bias, 3 = swish
template<int EPI, bool CAUSAL_K>
__global__ __launch_bounds__(256)
void sgemm_nn(const float* __restrict__ A, const float* __restrict__ B,
              float* __restrict__ C, int M, int N, int K,
              const float* __restrict__ res, const float* __restrict__ bias,
              long strideA, long strideB, long strideC)
{
    const int b = blockIdx.z;
    A += (long)b * strideA;
    B += (long)b * strideB;
    C += (long)b * strideC;
    const float* R = res ? res + (long)b * strideC : nullptr;

    const int crow = blockIdx.y * BM;
    const int ccol = blockIdx.x * BN;

    int Keff = K;
    if (CAUSAL_K) { int lim = crow + BM; if (lim < Keff) Keff = lim; }

    __shared__ float As[BKD * BM];
    __shared__ float Bs[BKD * BN];

    const int tid = threadIdx.x;
    const int tc  = tid % (BN / TN);   // 0..15
    const int tr  = tid / (BN / TN);   // 0..15
    const int iRA = tid / 2;           // 0..127  (row within A tile)
    const int iCA = tid % 2;           // which float4 of the 8 k's
    const int iRB = tid / 32;          // 0..7    (k within B tile)
    const int iCB = tid % 32;          // float4 col

    float acc[TM * TN];
    #pragma unroll
    for (int i = 0; i < TM * TN; i++) acc[i] = 0.f;
    float rM[TM], rN[TN];

    const float* Ap = A + (long)crow * K;
    const float* Bp = B + ccol;

    for (int kk = 0; kk < Keff; kk += BKD) {
        float4 a = *reinterpret_cast<const float4*>(&Ap[(long)iRA * K + kk + iCA * 4]);
        As[(iCA * 4 + 0) * BM + iRA] = a.x;
        As[(iCA * 4 + 1) * BM + iRA] = a.y;
        As[(iCA * 4 + 2) * BM + iRA] = a.z;
        As[(iCA * 4 + 3) * BM + iRA] = a.w;
        *reinterpret_cast<float4*>(&Bs[iRB * BN + iCB * 4]) =
            *reinterpret_cast<const float4*>(&Bp[(long)(kk + iRB) * N + iCB * 4]);
        __syncthreads();
        #pragma unroll
        for (int k = 0; k < BKD; k++) {
            #pragma unroll
            for (int i = 0; i < TM; i++) rM[i] = As[k * BM + tr * TM + i];
            #pragma unroll
            for (int j = 0; j < TN; j++) rN[j] = Bs[k * BN + tc * TN + j];
            #pragma unroll
            for (int i = 0; i < TM; i++)
                #pragma unroll
                for (int j = 0; j < TN; j++)
                    acc[i * TN + j] += rM[i] * rN[j];
        }
        __syncthreads();
    }

    #pragma unroll
    for (int i = 0; i < TM; i++) {
        const long r = crow + tr * TM + i;
        #pragma unroll
        for (int j = 0; j < TN; j += 4) {
            const int c = ccol + tc * TN + j;
            float4 v = make_float4(acc[i * TN + j], acc[i * TN + j + 1],
                                   acc[i * TN + j + 2], acc[i * TN + j + 3]);
            if (EPI == 1) {
                float4 rr = *reinterpret_cast<const float4*>(&R[r * N + c]);
                v.x += rr.x; v.y += rr.y; v.z += rr.z; v.w += rr.w;
            } else if (EPI == 2) {
                v.x += bias[c]; v.y += bias[c + 1]; v.z += bias[c + 2]; v.w += bias[c + 3];
            } else if (EPI == 3) {
                v.x = v.x / (1.f + __expf(-v.x));
                v.y = v.y / (1.f + __expf(-v.y));
                v.z = v.z / (1.f + __expf(-v.z));
                v.w = v.w / (1.f + __expf(-v.w));
            }
            *reinterpret_cast<float4*>(&C[r * N + c]) = v;
        }
    }
}

// ---------------- scores = alpha * Q Q^T, skip tiles fully above diagonal ---
__global__ __launch_bounds__(256)
void sgemm_nt_causal(const float* __restrict__ Q, float* __restrict__ Sc,
                     int S, int D, float alpha)
{
    const int b = blockIdx.z;
    const float* A = Q + (long)b * S * D;
    float* C = Sc + (long)b * S * S;

    const int crow = blockIdx.y * BM;
    const int ccol = blockIdx.x * BN;
    if (ccol >= crow + BM) return;   // fully masked tile; softmax writes 0 there

    __shared__ float As[BKD * BM];
    __shared__ float Bs[BKD * BN];

    const int tid = threadIdx.x;
    const int tc  = tid % 16;
    const int tr  = tid / 16;
    const int iR  = tid / 2;
    const int iC  = tid % 2;

    float acc[TM * TN];
    #pragma unroll
    for (int i = 0; i < TM * TN; i++) acc[i] = 0.f;
    float rM[TM], rN[TN];

    for (int kk = 0; kk < D; kk += BKD) {
        float4 a = *reinterpret_cast<const float4*>(&A[(long)(crow + iR) * D + kk + iC * 4]);
        As[(iC * 4 + 0) * BM + iR] = a.x;
        As[(iC * 4 + 1) * BM + iR] = a.y;
        As[(iC * 4 + 2) * BM + iR] = a.z;
        As[(iC * 4 + 3) * BM + iR] = a.w;
        float4 bb = *reinterpret_cast<const float4*>(&A[(long)(ccol + iR) * D + kk + iC * 4]);
        Bs[(iC * 4 + 0) * BN + iR] = bb.x;
        Bs[(iC * 4 + 1) * BN + iR] = bb.y;
        Bs[(iC * 4 + 2) * BN + iR] = bb.z;
        Bs[(iC * 4 + 3) * BN + iR] = bb.w;
        __syncthreads();
        #pragma unroll
        for (int k = 0; k < BKD; k++) {
            #pragma unroll
            for (int i = 0; i < TM; i++) rM[i] = As[k * BM + tr * TM + i];
            #pragma unroll
            for (int j = 0; j < TN; j++) rN[j] = Bs[k * BN + tc * TN + j];
            #pragma unroll
            for (int i = 0; i < TM; i++)
                #pragma unroll
                for (int j = 0; j < TN; j++)
                    acc[i * TN + j] += rM[i] * rN[j];
        }
        __syncthreads();
    }

    #pragma unroll
    for (int i = 0; i < TM; i++) {
        const long r = crow + tr * TM + i;
        #pragma unroll
        for (int j = 0; j < TN; j += 4) {
            const int c = ccol + tc * TN + j;
            float4 v = make_float4(acc[i * TN + j] * alpha, acc[i * TN + j + 1] * alpha,
                                   acc[i * TN + j + 2] * alpha, acc[i * TN + j + 3] * alpha);
            *reinterpret_cast<float4*>(&C[r * S + c]) = v;
        }
    }
}

// ---------------- causal softmax over row i (cols 0..i), zero the rest ------
__global__ __launch_bounds__(256)
void softmax_causal(float* __restrict__ scores, int S)
{
    const int gr = blockIdx.x;
    const int b = gr / S;
    const int i = gr % S;
    float* row = scores + (long)b * S * S + (long)i * S;
    const int n = i + 1;
    const int tid = threadIdx.x;
    __shared__ float red[256];

    float m = -3.0e38f;
    for (int j = tid; j < n; j += 256) m = fmaxf(m, row[j]);
    red[tid] = m; __syncthreads();
    for (int s = 128; s > 0; s >>= 1) { if (tid < s) red[tid] = fmaxf(red[tid], red[tid + s]); __syncthreads(); }
    m = red[0]; __syncthreads();

    float sum = 0.f;
    for (int j = tid; j < n; j += 256) { float e = __expf(row[j] - m); row[j] = e; sum += e; }
    red[tid] = sum; __syncthreads();
    for (int s = 128; s > 0; s >>= 1) { if (tid < s) red[tid] += red[tid + s]; __syncthreads(); }
    const float inv = 1.f / red[0];

    for (int j = tid; j < n; j += 256) row[j] *= inv;
    for (int j = n + tid; j < S; j += 256) row[j] = 0.f;
}

// ---------------- LayerNorm (no scale/bias), N = 1024, 256 threads ---------
__global__ __launch_bounds__(256)
void layernorm_rows(const float* __restrict__ in, float* __restrict__ out, int N)
{
    const long r = blockIdx.x;
    const float* x = in + r * N;
    float* y = out + r * N;
    const int tid = threadIdx.x;
    __shared__ float rs[256], rss[256];

    float4 a = *reinterpret_cast<const float4*>(&x[tid * 4]);
    float s  = a.x + a.y + a.z + a.w;
    float ss = a.x * a.x + a.y * a.y + a.z * a.z + a.w * a.w;
    rs[tid] = s; rss[tid] = ss; __syncthreads();
    for (int k = 128; k > 0; k >>= 1) {
        if (tid < k) { rs[tid] += rs[tid + k]; rss[tid] += rss[tid + k]; }
        __syncthreads();
    }
    const float mean = rs[0] / N;
    const float msq  = rss[0] / N;
    const float rstd = rsqrtf(msq - mean * mean + EPSLN);
    float4 v = make_float4((a.x - mean) * rstd, (a.y - mean) * rstd,
                           (a.z - mean) * rstd, (a.w - mean) * rstd);
    *reinterpret_cast<float4*>(&y[tid * 4]) = v;
}

// ---------------- W_eff[d,j] = sum_h out_kernel[h*D+d, j] ------------------
__global__ void reduce_wout(const float* __restrict__ wout, float* __restrict__ weff,
                            int DD, int H)
{
    const int idx = blockIdx.x * blockDim.x + threadIdx.x;
    if (idx < DD) {
        float s = 0.f;
        for (int h = 0; h < H; h++) s += wout[(long)h * DD + idx];
        weff[idx] = s;
    }
}

extern "C" void kernel_launch(void* const* d_in, const int* in_sizes, int n_in,
                              void* d_out, int out_size)
{
    const float* x    = (const float*)d_in[0];
    // d_in[1] = mask (known causal tril; not needed)
    const float* wi   = (const float*)d_in[2];
    const float* wout = (const float*)d_in[3];
    const float* bias = (const float*)d_in[4];
    float* out = (float*)d_out;

    float *q, *sc, *head, *h, *t, *weff;
    cudaGetSymbolAddress((void**)&q,    g_q);
    cudaGetSymbolAddress((void**)&sc,   g_sc);
    cudaGetSymbolAddress((void**)&head, g_head);
    cudaGetSymbolAddress((void**)&h,    g_h);
    cudaGetSymbolAddress((void**)&t,    g_t);
    cudaGetSymbolAddress((void**)&weff, g_weff);

    const int Bb = BATCH, S = SEQ, D = DIM, H = HEADS, M = MROWS;
    const float alpha = 1.0f / 32.0f;   // 1/sqrt(1024)

    // 1. effective out-projection weight (tile-concat collapses to a sum)
    reduce_wout<<<(D * D + 255) / 256, 256>>>(wout, weff, D * D, H);

    // 2. q = x @ wi   (q == k == v, shared weights)
    sgemm_nn<0, false><<<dim3(D / BN, M / BM, 1), 256>>>(
        x, wi, q, M, D, D, nullptr, nullptr, 0, 0, 0);

    // 3. scores = alpha * q q^T (causal tiles only)
    sgemm_nt_causal<<<dim3(S / BN, S / BM, Bb), 256>>>(q, sc, S, D, alpha);

    // 4. causal softmax (writes exact zeros above diagonal)
    softmax_causal<<<Bb * S, 256>>>(sc, S);

    // 5. head = q + P @ q   (K clamped to causal extent per row block)
    sgemm_nn<1, true><<<dim3(D / BN, S / BM, Bb), 256>>>(
        sc, q, head, S, D, S, q, nullptr,
        (long)S * S, (long)S * D, (long)S * D);

    // 6. h = head @ W_eff + bias
    sgemm_nn<2, false><<<dim3(D / BN, M / BM, 1), 256>>>(
        head, weff, h, M, D, D, nullptr, bias, 0, 0, 0);

    // 7. LayerNorm (in-place safe: all reads precede writes within a block)
    layernorm_rows<<<M, 256>>>(h, h, D);

    // 8. t = swish(h @ wi)
    sgemm_nn<3, false><<<dim3(D / BN, M / BM, 1), 256>>>(
        h, wi, t, M, D, D, nullptr, nullptr, 0, 0, 0);

    // 9. out = t @ wi
    sgemm_nn<0, false><<<dim3(D / BN, M / BM, 1), 256>>>(
        t, wi, out, M, D, D, nullptr, nullptr, 0, 0, 0);
}

// round 3
// speedup vs baseline: 2.0983x; 2.0983x over previous
#include <cuda_runtime.h>
#include <cuda_bf16.h>
#include <cstdint>
#include <math.h>

#define BATCH 2
#define SEQ   2048
#define DIM   1024
#define HEADS 8
#define MROWS (BATCH*SEQ)
#define EPSLN 1e-5f

typedef __nv_bfloat16  bf16;
typedef __nv_bfloat162 bf162;

// ---------------- scratch (device globals; no allocation allowed) ----------
__device__ float g_q [MROWS*DIM];
__device__ float g_sc[BATCH*SEQ*SEQ];
__device__ float g_h [MROWS*DIM];
__device__ bf16 g_xh [MROWS*DIM], g_xl [MROWS*DIM];
__device__ bf16 g_qh [MROWS*DIM], g_ql [MROWS*DIM];
__device__ bf16 g_qTh[MROWS*DIM], g_qTl[MROWS*DIM];   // [B][D][S]
__device__ bf16 g_ph [BATCH*SEQ*SEQ], g_pl [BATCH*SEQ*SEQ];
__device__ bf16 g_hdh[MROWS*DIM], g_hdl[MROWS*DIM];
__device__ bf16 g_hh [MROWS*DIM], g_hl [MROWS*DIM];
__device__ bf16 g_th [MROWS*DIM], g_tl [MROWS*DIM];
__device__ bf16 g_wiTh[DIM*DIM], g_wiTl[DIM*DIM];
__device__ bf16 g_weTh[DIM*DIM], g_weTl[DIM*DIM];

// ---------------- PTX helpers ----------------------------------------------
__device__ __forceinline__ uint32_t smem_u32(const void* p) {
    uint32_t a;
    asm("{ .reg .u64 t; cvta.to.shared.u64 t, %1; cvt.u32.u64 %0, t; }" : "=r"(a) : "l"(p));
    return a;
}
__device__ __forceinline__ void ldsm4(uint32_t& r0, uint32_t& r1, uint32_t& r2, uint32_t& r3,
                                      uint32_t addr) {
    asm volatile("ldmatrix.sync.aligned.m8n8.x4.shared.b16 {%0,%1,%2,%3}, [%4];"
                 : "=r"(r0), "=r"(r1), "=r"(r2), "=r"(r3) : "r"(addr));
}
__device__ __forceinline__ void mma16816(float* d, const uint32_t* a, const uint32_t* b) {
    asm volatile(
        "mma.sync.aligned.m16n8k16.row.col.f32.bf16.bf16.f32 "
        "{%0,%1,%2,%3}, {%4,%5,%6,%7}, {%8,%9}, {%0,%1,%2,%3};"
        : "+f"(d[0]), "+f"(d[1]), "+f"(d[2]), "+f"(d[3])
        : "r"(a[0]), "r"(a[1]), "r"(a[2]), "r"(a[3]), "r"(b[0]), "r"(b[1]));
}
__device__ __forceinline__ void cp16(uint32_t dst, const void* src) {
    asm volatile("cp.async.cg.shared.global [%0], [%1], 16;" :: "r"(dst), "l"(src));
}
#define CP_COMMIT() asm volatile("cp.async.commit_group;" ::: "memory")
#define CP_WAIT1()  asm volatile("cp.async.wait_group 1;" ::: "memory")

__device__ __forceinline__ void split1(float v, bf16& h, bf16& l) {
    h = __float2bfloat16(v);
    l = __float2bfloat16(v - __bfloat162float(h));
}

// ---------------- HMMA bf16-split GEMM --------------------------------------
// C[M,N](fp32) = A[M,K] * B^T ; A,B given as hi/lo bf16 row-major ([M,K],[N,K]).
// 3 passes: AhBh + AhBl + AlBh accumulated in fp32 registers.
#define BMM 128
#define BNN 128
#define BKK 64
#define KPAD 72                       // elements per smem row (64 + 8 pad)
#define ROWB (KPAD*2)                 // 144 bytes per row
#define ABYTES (128*ROWB)             // 18432 per buffer
#define STAGE  (4*ABYTES)             // Ah,Al,Bh,Bl
#define GEMM_SMEM (2*STAGE)           // 147456

// EPI: 0 fp32 | 1 alpha*fp32 | 2 res-add + split | 3 +bias fp32 | 4 swish+split | 5 fp32+split
// CAUSAL: 0 none | 1 skip tiles above diagonal | 2 clamp K to crow+BMM
template<int EPI, int CAUSAL>
__global__ __launch_bounds__(256, 1)
void hmma_gemm(const bf16* __restrict__ Ah, const bf16* __restrict__ Al,
               const bf16* __restrict__ Bh, const bf16* __restrict__ Bl,
               float* __restrict__ C, bf16* __restrict__ Ch, bf16* __restrict__ Cl,
               const float* __restrict__ res, const float* __restrict__ bias,
               int M, int N, int K, float alpha, long sA, long sB, long sC)
{
    const int crow = blockIdx.y * BMM;
    const int ccol = blockIdx.x * BNN;
    if (CAUSAL == 1 && ccol >= crow + BMM) return;

    const int b = blockIdx.z;
    Ah += (long)b * sA;  Al += (long)b * sA;
    Bh += (long)b * sB;  Bl += (long)b * sB;

    extern __shared__ char smem[];
    const uint32_t sb = smem_u32(smem);
    const int tid  = threadIdx.x;
    const int lane = tid & 31;
    const int wid  = tid >> 5;
    const int wm   = wid & 1;        // 2 m-slices of 64
    const int wn   = wid >> 1;       // 4 n-slices of 32

    const int Keff = (CAUSAL == 2) ? (crow + BMM) : K;
    const int nC = Keff / BKK;

    // cp.async mapping: thread -> (row, 4 contiguous 16B chunks)
    const int r  = tid >> 1;
    const int c0 = (tid & 1) * 4;    // chunk base (each chunk = 8 bf16 = 16B)
    const bf16* pAh = Ah + (long)(crow + r) * K + c0 * 8;
    const bf16* pAl = Al + (long)(crow + r) * K + c0 * 8;
    const bf16* pBh = Bh + (long)(ccol + r) * K + c0 * 8;
    const bf16* pBl = Bl + (long)(ccol + r) * K + c0 * 8;
    const uint32_t dstoff = r * ROWB + c0 * 16;

    // ldmatrix per-thread base addresses (A buffer / Bh buffer)
    const uint32_t aAddr = sb + (wm * 64 + (lane & 15)) * ROWB + (lane >> 4) * 16;
    const uint32_t bAddr = sb + 2 * ABYTES +
                           (wn * 32 + ((lane >> 4) << 3) + (lane & 7)) * ROWB +
                           ((lane >> 3) & 1) * 16;

    float acc[4][4][4];
    #pragma unroll
    for (int i = 0; i < 4; i++)
        #pragma unroll
        for (int j = 0; j < 4; j++)
            #pragma unroll
            for (int k = 0; k < 4; k++) acc[i][j][k] = 0.f;

    // prefetch chunk 0
    {
        const uint32_t st = sb + dstoff;
        #pragma unroll
        for (int i = 0; i < 4; i++) {
            cp16(st + i * 16,              pAh + i * 8);
            cp16(st + ABYTES + i * 16,     pAl + i * 8);
            cp16(st + 2 * ABYTES + i * 16, pBh + i * 8);
            cp16(st + 3 * ABYTES + i * 16, pBl + i * 8);
        }
        CP_COMMIT();
    }

    for (int c = 0; c < nC; c++) {
        if (c + 1 < nC) {
            const uint32_t st = sb + ((c + 1) & 1) * STAGE + dstoff;
            const long ke = (long)(c + 1) * BKK;
            #pragma unroll
            for (int i = 0; i < 4; i++) {
                cp16(st + i * 16,              pAh + ke + i * 8);
                cp16(st + ABYTES + i * 16,     pAl + ke + i * 8);
                cp16(st + 2 * ABYTES + i * 16, pBh + ke + i * 8);
                cp16(st + 3 * ABYTES + i * 16, pBl + ke + i * 8);
            }
        }
        CP_COMMIT();
        CP_WAIT1();
        __syncthreads();

        const uint32_t stg = (c & 1) * STAGE;
        #pragma unroll
        for (int ks = 0; ks < 4; ks++) {
            uint32_t ah[4][4], al[4][4], bh[4][2], bl[4][2];
            #pragma unroll
            for (int mt = 0; mt < 4; mt++) {
                const uint32_t ad = aAddr + stg + mt * (16 * ROWB) + ks * 32;
                ldsm4(ah[mt][0], ah[mt][1], ah[mt][2], ah[mt][3], ad);
                ldsm4(al[mt][0], al[mt][1], al[mt][2], al[mt][3], ad + ABYTES);
            }
            #pragma unroll
            for (int pr = 0; pr < 2; pr++) {
                const uint32_t bd = bAddr + stg + pr * (16 * ROWB) + ks * 32;
                uint32_t r0, r1, r2, r3;
                ldsm4(r0, r1, r2, r3, bd);
                bh[2*pr][0] = r0; bh[2*pr][1] = r1; bh[2*pr+1][0] = r2; bh[2*pr+1][1] = r3;
                ldsm4(r0, r1, r2, r3, bd + ABYTES);
                bl[2*pr][0] = r0; bl[2*pr][1] = r1; bl[2*pr+1][0] = r2; bl[2*pr+1][1] = r3;
            }
            #pragma unroll
            for (int mt = 0; mt < 4; mt++)
                #pragma unroll
                for (int nt = 0; nt < 4; nt++) {
                    mma16816(acc[mt][nt], ah[mt], bh[nt]);
                    mma16816(acc[mt][nt], ah[mt], bl[nt]);
                    mma16816(acc[mt][nt], al[mt], bh[nt]);
                }
        }
        __syncthreads();
    }

    // ---------------- epilogue ----------------
    const int g  = lane >> 2;
    const int tg = lane & 3;
    #pragma unroll
    for (int mt = 0; mt < 4; mt++)
        #pragma unroll
        for (int nt = 0; nt < 4; nt++)
            #pragma unroll
            for (int hh = 0; hh < 2; hh++) {
                const int row = crow + wm * 64 + mt * 16 + g + hh * 8;
                const int col = ccol + wn * 32 + nt * 8 + tg * 2;
                const long off = (long)b * sC + (long)row * N + col;
                float vx = acc[mt][nt][hh * 2 + 0];
                float vy = acc[mt][nt][hh * 2 + 1];
                if (EPI == 1) { vx *= alpha; vy *= alpha; }
                if (EPI == 2) {
                    const float2 r2 = *reinterpret_cast<const float2*>(res + off);
                    vx += r2.x; vy += r2.y;
                }
                if (EPI == 3) { vx += bias[col]; vy += bias[col + 1]; }
                if (EPI == 4) {
                    vx = vx / (1.f + __expf(-vx));
                    vy = vy / (1.f + __expf(-vy));
                }
                if (EPI == 0 || EPI == 1 || EPI == 3 || EPI == 5) {
                    float2 o; o.x = vx; o.y = vy;
                    *reinterpret_cast<float2*>(C + off) = o;
                }
                if (EPI == 2 || EPI == 4 || EPI == 5) {
                    bf16 h0, l0, h1, l1;
                    split1(vx, h0, l0); split1(vy, h1, l1);
                    bf162 hp; hp.x = h0; hp.y = h1;
                    bf162 lp; lp.x = l0; lp.y = l1;
                    *reinterpret_cast<bf162*>(Ch + off) = hp;
                    *reinterpret_cast<bf162*>(Cl + off) = lp;
                }
            }
}

// ---------------- fp32 -> hi/lo bf16 split ---------------------------------
__global__ __launch_bounds__(256)
void split_f32(const float* __restrict__ in, bf16* __restrict__ oh, bf16* __restrict__ ol)
{
    const long i4 = (long)(blockIdx.x * 256 + threadIdx.x) * 4;
    const float4 v = *reinterpret_cast<const float4*>(in + i4);
    bf16 h0, l0, h1, l1, h2, l2, h3, l3;
    split1(v.x, h0, l0); split1(v.y, h1, l1); split1(v.z, h2, l2); split1(v.w, h3, l3);
    bf162 a; a.x = h0; a.y = h1;  bf162 b; b.x = h2; b.y = h3;
    bf162 c; c.x = l0; c.y = l1;  bf162 d; d.x = l2; d.y = l3;
    *reinterpret_cast<bf162*>(oh + i4)     = a;
    *reinterpret_cast<bf162*>(oh + i4 + 2) = b;
    *reinterpret_cast<bf162*>(ol + i4)     = c;
    *reinterpret_cast<bf162*>(ol + i4 + 2) = d;
}

// ---------------- transpose + split: out[c][r] = in[r][c] -------------------
__global__ __launch_bounds__(256)
void transpose_split(const float* __restrict__ in, bf16* __restrict__ oh, bf16* __restrict__ ol,
                     int R, int Cc, long sIn, long sOut)
{
    __shared__ float tile[32][33];
    const int b = blockIdx.z;
    const int col0 = blockIdx.x * 32, row0 = blockIdx.y * 32;
    const int tx = threadIdx.x, ty = threadIdx.y;
    #pragma unroll
    for (int i = 0; i < 4; i++) {
        const int lr = ty + i * 8;
        tile[lr][tx] = in[(long)b * sIn + (long)(row0 + lr) * Cc + col0 + tx];
    }
    __syncthreads();
    #pragma unroll
    for (int i = 0; i < 4; i++) {
        const int lc = ty + i * 8;
        const float v = tile[tx][lc];
        bf16 h, l; split1(v, h, l);
        const long o = (long)b * sOut + (long)(col0 + lc) * R + row0 + tx;
        oh[o] = h; ol[o] = l;
    }
}

// ---------------- weffT[j][d] = sum_h wout[h*D+d][j], split -----------------
__global__ __launch_bounds__(256)
void reduce_weffT(const float* __restrict__ wout, bf16* __restrict__ oh, bf16* __restrict__ ol)
{
    __shared__ float tile[32][33];
    const int j0 = blockIdx.x * 32, d0 = blockIdx.y * 32;
    const int tx = threadIdx.x, ty = threadIdx.y;
    #pragma unroll
    for (int i = 0; i < 4; i++) {
        const int ld = ty + i * 8;
        float s = 0.f;
        #pragma unroll
        for (int h = 0; h < HEADS; h++)
            s += wout[(long)h * DIM * DIM + (long)(d0 + ld) * DIM + j0 + tx];
        tile[ld][tx] = s;
    }
    __syncthreads();
    #pragma unroll
    for (int i = 0; i < 4; i++) {
        const int lj = ty + i * 8;
        const float v = tile[tx][lj];
        bf16 h, l; split1(v, h, l);
        const long o = (long)(j0 + lj) * DIM + d0 + tx;
        oh[o] = h; ol[o] = l;
    }
}

// ---------------- causal softmax: fp32 scores -> split P --------------------
__global__ __launch_bounds__(256)
void softmax_split(float* __restrict__ sc, bf16* __restrict__ ph, bf16* __restrict__ pl, int S)
{
    const int gr = blockIdx.x;
    const int b = gr / S, i = gr % S;
    float* row = sc + (long)b * S * S + (long)i * S;
    bf16* rh = ph + (long)b * S * S + (long)i * S;
    bf16* rl = pl + (long)b * S * S + (long)i * S;
    const int n = i + 1;
    const int tid = threadIdx.x;
    __shared__ float red[256];

    float m = -3.0e38f;
    for (int j = tid; j < n; j += 256) m = fmaxf(m, row[j]);
    red[tid] = m; __syncthreads();
    for (int s = 128; s > 0; s >>= 1) { if (tid < s) red[tid] = fmaxf(red[tid], red[tid + s]); __syncthreads(); }
    m = red[0]; __syncthreads();

    float sum = 0.f;
    for (int j = tid; j < n; j += 256) { const float e = __expf(row[j] - m); row[j] = e; sum += e; }
    red[tid] = sum; __syncthreads();
    for (int s = 128; s > 0; s >>= 1) { if (tid < s) red[tid] += red[tid + s]; __syncthreads(); }
    const float inv = 1.f / red[0];

    for (int j = tid; j < n; j += 256) {
        const float p = row[j] * inv;
        bf16 h, l; split1(p, h, l);
        rh[j] = h; rl[j] = l;
    }
    const bf16 z = __float2bfloat16(0.f);
    for (int j = n + tid; j < S; j += 256) { rh[j] = z; rl[j] = z; }
}

// ---------------- LayerNorm -> split ----------------------------------------
__global__ __launch_bounds__(256)
void layernorm_split(const float* __restrict__ in, bf16* __restrict__ oh, bf16* __restrict__ ol, int N)
{
    const long r = blockIdx.x;
    const float* x = in + r * N;
    const int tid = threadIdx.x;
    __shared__ float rs[256], rss[256];

    const float4 a = *reinterpret_cast<const float4*>(&x[tid * 4]);
    rs[tid]  = a.x + a.y + a.z + a.w;
    rss[tid] = a.x * a.x + a.y * a.y + a.z * a.z + a.w * a.w;
    __syncthreads();
    for (int k = 128; k > 0; k >>= 1) {
        if (tid < k) { rs[tid] += rs[tid + k]; rss[tid] += rss[tid + k]; }
        __syncthreads();
    }
    const float mean = rs[0] / N;
    const float msq  = rss[0] / N;
    const float rstd = rsqrtf(msq - mean * mean + EPSLN);
    const float v0 = (a.x - mean) * rstd, v1 = (a.y - mean) * rstd;
    const float v2 = (a.z - mean) * rstd, v3 = (a.w - mean) * rstd;
    bf16 h0, l0, h1, l1, h2, l2, h3, l3;
    split1(v0, h0, l0); split1(v1, h1, l1); split1(v2, h2, l2); split1(v3, h3, l3);
    bf162 p0; p0.x = h0; p0.y = h1;
    bf162 p1; p1.x = h2; p1.y = h3;
    bf162 q0; q0.x = l0; q0.y = l1;
    bf162 q1; q1.x = l2; q1.y = l3;
    *reinterpret_cast<bf162*>(oh + r * N + tid * 4)     = p0;
    *reinterpret_cast<bf162*>(oh + r * N + tid * 4 + 2) = p1;
    *reinterpret_cast<bf162*>(ol + r * N + tid * 4)     = q0;
    *reinterpret_cast<bf162*>(ol + r * N + tid * 4 + 2) = q1;
}

// ---------------------------------------------------------------------------
extern "C" void kernel_launch(void* const* d_in, const int* in_sizes, int n_in,
                              void* d_out, int out_size)
{
    const float* x    = (const float*)d_in[0];
    const float* wi   = (const float*)d_in[2];
    const float* wout = (const float*)d_in[3];
    const float* bias = (const float*)d_in[4];
    float* out = (float*)d_out;

    float *q, *sc, *h;
    bf16 *xh, *xl, *qh, *ql, *qTh, *qTl, *ph, *pl, *hdh, *hdl, *hh, *hl, *th, *tl;
    bf16 *wiTh, *wiTl, *weTh, *weTl;
    cudaGetSymbolAddress((void**)&q, g_q);     cudaGetSymbolAddress((void**)&sc, g_sc);
    cudaGetSymbolAddress((void**)&h, g_h);
    cudaGetSymbolAddress((void**)&xh, g_xh);   cudaGetSymbolAddress((void**)&xl, g_xl);
    cudaGetSymbolAddress((void**)&qh, g_qh);   cudaGetSymbolAddress((void**)&ql, g_ql);
    cudaGetSymbolAddress((void**)&qTh, g_qTh); cudaGetSymbolAddress((void**)&qTl, g_qTl);
    cudaGetSymbolAddress((void**)&ph, g_ph);   cudaGetSymbolAddress((void**)&pl, g_pl);
    cudaGetSymbolAddress((void**)&hdh, g_hdh); cudaGetSymbolAddress((void**)&hdl, g_hdl);
    cudaGetSymbolAddress((void**)&hh, g_hh);   cudaGetSymbolAddress((void**)&hl, g_hl);
    cudaGetSymbolAddress((void**)&th, g_th);   cudaGetSymbolAddress((void**)&tl, g_tl);
    cudaGetSymbolAddress((void**)&wiTh, g_wiTh); cudaGetSymbolAddress((void**)&wiTl, g_wiTl);
    cudaGetSymbolAddress((void**)&weTh, g_weTh); cudaGetSymbolAddress((void**)&weTl, g_weTl);

    cudaFuncSetAttribute(hmma_gemm<5,0>, cudaFuncAttributeMaxDynamicSharedMemorySize, GEMM_SMEM);
    cudaFuncSetAttribute(hmma_gemm<1,1>, cudaFuncAttributeMaxDynamicSharedMemorySize, GEMM_SMEM);
    cudaFuncSetAttribute(hmma_gemm<2,2>, cudaFuncAttributeMaxDynamicSharedMemorySize, GEMM_SMEM);
    cudaFuncSetAttribute(hmma_gemm<3,0>, cudaFuncAttributeMaxDynamicSharedMemorySize, GEMM_SMEM);
    cudaFuncSetAttribute(hmma_gemm<4,0>, cudaFuncAttributeMaxDynamicSharedMemorySize, GEMM_SMEM);
    cudaFuncSetAttribute(hmma_gemm<0,0>, cudaFuncAttributeMaxDynamicSharedMemorySize, GEMM_SMEM);

    const int S = SEQ, D = DIM, M = MROWS;
    const float alpha = 1.0f / 32.0f;   // 1/sqrt(1024)
    const long SD = (long)S * D, SS = (long)S * S;

    // prep: weight transposes/splits + x split
    reduce_weffT<<<dim3(32, 32, 1), dim3(32, 8)>>>(wout, weTh, weTl);
    transpose_split<<<dim3(32, 32, 1), dim3(32, 8)>>>(wi, wiTh, wiTl, D, D, 0, 0);
    split_f32<<<M * D / 1024, 256>>>(x, xh, xl);

    // q = x @ wi  (fp32 + splits)
    hmma_gemm<5,0><<<dim3(D/BNN, M/BMM, 1), 256, GEMM_SMEM>>>(
        xh, xl, wiTh, wiTl, q, qh, ql, nullptr, nullptr, M, D, D, 0.f, 0, 0, 0);

    // qT splits (per batch)
    transpose_split<<<dim3(D/32, S/32, BATCH), dim3(32, 8)>>>(q, qTh, qTl, S, D, SD, SD);

    // scores = alpha * q q^T  (causal tiles only)
    hmma_gemm<1,1><<<dim3(S/BNN, S/BMM, BATCH), 256, GEMM_SMEM>>>(
        qh, ql, qh, ql, sc, nullptr, nullptr, nullptr, nullptr, S, S, D, alpha, SD, SD, SS);

    // softmax -> P splits
    softmax_split<<<BATCH * S, 256>>>(sc, ph, pl, S);

    // head = P @ q + q  (splits out; K clamped causally)
    hmma_gemm<2,2><<<dim3(D/BNN, S/BMM, BATCH), 256, GEMM_SMEM>>>(
        ph, pl, qTh, qTl, nullptr, hdh, hdl, q, nullptr, S, D, S, 0.f, SS, SD, SD);

    // h = head @ W_eff + bias  (fp32)
    hmma_gemm<3,0><<<dim3(D/BNN, M/BMM, 1), 256, GEMM_SMEM>>>(
        hdh, hdl, weTh, weTl, h, nullptr, nullptr, nullptr, bias, M, D, D, 0.f, 0, 0, 0);

    // LayerNorm -> splits
    layernorm_split<<<M, 256>>>(h, hh, hl, D);

    // t = swish(h @ wi)  (splits out)
    hmma_gemm<4,0><<<dim3(D/BNN, M/BMM, 1), 256, GEMM_SMEM>>>(
        hh, hl, wiTh, wiTl, nullptr, th, tl, nullptr, nullptr, M, D, D, 0.f, 0, 0, 0);

    // out = t @ wi  (fp32)
    hmma_gemm<0,0><<<dim3(D/BNN, M/BMM, 1), 256, GEMM_SMEM>>>(
        th, tl, wiTh, wiTl, out, nullptr, nullptr, nullptr, nullptr, M, D, D, 0.f, 0, 0, 0);
}